// round 8
// baseline (speedup 1.0000x reference)
#include <cuda_runtime.h>
#include <cuda_bf16.h>
#include <math.h>

typedef __nv_bfloat16 bf16;

#define SEQ   2048
#define HID   4096
#define NQH   32
#define NKVH  8
#define HD    128
#define KVD   1024
#define QKVN  6144   // 4096 + 2*1024

// ------------------------- device scratch (no allocation allowed) ----------
__device__ __align__(16) bf16 g_hid_hi[(size_t)SEQ * HID];
__device__ __align__(16) bf16 g_hid_lo[(size_t)SEQ * HID];
__device__ __align__(16) bf16 g_wqkvT_hi[(size_t)QKVN * HID];   // [N][K]
__device__ __align__(16) bf16 g_wqkvT_lo[(size_t)QKVN * HID];
__device__ __align__(16) bf16 g_wprojT_hi[(size_t)HID * HID];   // [N][K]
__device__ __align__(16) bf16 g_wprojT_lo[(size_t)HID * HID];
__device__ __align__(16) float g_qkv[(size_t)SEQ * QKVN];
__device__ __align__(16) bf16 g_qkv_hi[(size_t)SEQ * QKVN];
__device__ __align__(16) bf16 g_qkv_lo[(size_t)SEQ * QKVN];
__device__ __align__(16) bf16 g_vt_hi[(size_t)NKVH * HD * SEQ]; // [h][d][t]
__device__ __align__(16) bf16 g_vt_lo[(size_t)NKVH * HD * SEQ];
__device__ __align__(16) bf16 g_attn_hi[(size_t)SEQ * HID];
__device__ __align__(16) bf16 g_attn_lo[(size_t)SEQ * HID];

// ------------------------- PTX helpers --------------------------------------
__device__ __forceinline__ void mma16816(float* c, const unsigned* a, const unsigned* b)
{
    asm volatile(
        "mma.sync.aligned.m16n8k16.row.col.f32.bf16.bf16.f32 "
        "{%0,%1,%2,%3}, {%4,%5,%6,%7}, {%8,%9}, {%0,%1,%2,%3};\n"
        : "+f"(c[0]), "+f"(c[1]), "+f"(c[2]), "+f"(c[3])
        : "r"(a[0]), "r"(a[1]), "r"(a[2]), "r"(a[3]), "r"(b[0]), "r"(b[1]));
}
__device__ __forceinline__ void ldsm4(unsigned& r0, unsigned& r1, unsigned& r2, unsigned& r3,
                                      unsigned addr)
{
    asm volatile("ldmatrix.sync.aligned.m8n8.x4.shared.b16 {%0,%1,%2,%3}, [%4];\n"
                 : "=r"(r0), "=r"(r1), "=r"(r2), "=r"(r3) : "r"(addr));
}
#define CP16(dst, src) \
    asm volatile("cp.async.cg.shared.global [%0], [%1], 16;\n" :: "r"(dst), "l"(src))
#define CP_COMMIT() asm volatile("cp.async.commit_group;\n")
#define CP_WAIT1()  asm volatile("cp.async.wait_group 1;\n")
#define CP_WAIT0()  asm volatile("cp.async.wait_group 0;\n")

__device__ __forceinline__ void pack_hl(float a, float b, unsigned& h, unsigned& l)
{
    bf16 ha = __float2bfloat16(a), hb = __float2bfloat16(b);
    __nv_bfloat162 hh; hh.x = ha; hh.y = hb;
    h = *(unsigned*)&hh;
    bf16 la = __float2bfloat16(a - __bfloat162float(ha));
    bf16 lb = __float2bfloat16(b - __bfloat162float(hb));
    __nv_bfloat162 ll; ll.x = la; ll.y = lb;
    l = *(unsigned*)&ll;
}

// ------------------------- split fp32 -> (hi, lo) bf16 ----------------------
__global__ void split_f32(const float* __restrict__ in,
                          bf16* __restrict__ hi, bf16* __restrict__ lo, size_t n)
{
    size_t i = ((size_t)blockIdx.x * blockDim.x + threadIdx.x) * 4;
    if (i >= n) return;
    float4 v = *(const float4*)(in + i);
    bf16 h0 = __float2bfloat16(v.x), h1 = __float2bfloat16(v.y);
    bf16 h2 = __float2bfloat16(v.z), h3 = __float2bfloat16(v.w);
    hi[i] = h0; hi[i+1] = h1; hi[i+2] = h2; hi[i+3] = h3;
    lo[i]   = __float2bfloat16(v.x - __bfloat162float(h0));
    lo[i+1] = __float2bfloat16(v.y - __bfloat162float(h1));
    lo[i+2] = __float2bfloat16(v.z - __bfloat162float(h2));
    lo[i+3] = __float2bfloat16(v.w - __bfloat162float(h3));
}

// -------- transposed split: in[k][n] fp32 -> out[n][k] (hi, lo) bf16 --------
__global__ void tsplit_f32(const float* __restrict__ in, int ldin, long long inZ,
                           bf16* __restrict__ hi, bf16* __restrict__ lo,
                           int ldout, long long outZ)
{
    __shared__ float t[32][33];
    const float* I = in + (size_t)blockIdx.z * inZ;
    bf16* H = hi + (size_t)blockIdx.z * outZ;
    bf16* L = lo + (size_t)blockIdx.z * outZ;
    const int k0 = blockIdx.y * 32, n0 = blockIdx.x * 32;
    const int tx = threadIdx.x, ty = threadIdx.y;   // 32 x 8
#pragma unroll
    for (int i = 0; i < 32; i += 8)
        t[ty + i][tx] = I[(size_t)(k0 + ty + i) * ldin + n0 + tx];
    __syncthreads();
#pragma unroll
    for (int i = 0; i < 32; i += 8) {
        float v = t[tx][ty + i];
        bf16 h = __float2bfloat16(v);
        size_t o = (size_t)(n0 + ty + i) * ldout + k0 + tx;
        H[o] = h;
        L[o] = __float2bfloat16(v - __bfloat162float(h));
    }
}

// ---------------------------------------------------------------------------
// Triple-product bf16 GEMM (dense projections), 128(M) x 256(N) tile, BK=32.
// 8 warps (2x4), warp tile 64x64. cp.async double-buffer, ldmatrix.
//   C = Ah*Bh + Ah*Bl + Al*Bh + bias
// A: [M,K] row-major. B: [N,K] row-major.
// smem stage: Ah@0 (10240) Al@10240 Bh@20480 (20480) Bl@40960 -> 61440 B
// ---------------------------------------------------------------------------
#define GP_STAGE 61440
#define GP_SMEM  (2 * GP_STAGE)   // 122880

__global__ __launch_bounds__(256, 1) void gemm3p(
    int K,
    const bf16* __restrict__ Ahi, const bf16* __restrict__ Alo, int lda,
    const bf16* __restrict__ Bhi, const bf16* __restrict__ Blo, int ldb,
    const float* __restrict__ bias,
    float* __restrict__ C, int ldc)
{
    const int bx = blockIdx.x, by = blockIdx.y;

    extern __shared__ bf16 smem[];
    const unsigned SB = (unsigned)__cvta_generic_to_shared(smem);

    float* Cb = C + (size_t)by * 128 * ldc + (size_t)bx * 256;

    const int tid  = threadIdx.x;
    const int warp = tid >> 5, lane = tid & 31;
    const int wm = warp >> 2, wn = warp & 3;        // 2 x 4 warps
    const int g = lane >> 2, t4 = lane & 3;
    const int arow = lane & 15, csel = (lane >> 4) << 3;

    const int r = tid >> 2;                         // 0..63
    const int ch = tid & 3;                         // 16B chunk

    const int nk = K >> 5;

    auto loadStage = [&](int s, int kt) {
        const int k0 = kt * 32 + ch * 8;
        const unsigned sb = SB + s * GP_STAGE;
        const unsigned dof = r * 80 + ch * 16;
        // A hi/lo: 128 rows
#pragma unroll
        for (int i = 0; i < 2; i++) {
            const int row = r + i * 64;
            const unsigned d = sb + dof + i * 64 * 80;
            CP16(d,         Ahi + (size_t)(by * 128 + row) * lda + k0);
            CP16(d + 10240, Alo + (size_t)(by * 128 + row) * lda + k0);
        }
        // B hi/lo: 256 rows
#pragma unroll
        for (int i = 0; i < 4; i++) {
            const int row = r + i * 64;
            const unsigned d = sb + 20480 + dof + i * 64 * 80;
            CP16(d,         Bhi + (size_t)(bx * 256 + row) * ldb + k0);
            CP16(d + 20480, Blo + (size_t)(bx * 256 + row) * ldb + k0);
        }
    };

    float acc[4][8][4];
#pragma unroll
    for (int i = 0; i < 4; i++)
#pragma unroll
        for (int j = 0; j < 8; j++)
#pragma unroll
            for (int q = 0; q < 4; q++) acc[i][j][q] = 0.f;

    loadStage(0, 0);
    CP_COMMIT();

    for (int kt = 0; kt < nk; kt++) {
        const int cur = kt & 1;
        if (kt + 1 < nk) { loadStage(cur ^ 1, kt + 1); CP_COMMIT(); CP_WAIT1(); }
        else            { CP_WAIT0(); }
        __syncthreads();

        const unsigned sb = SB + cur * GP_STAGE;
#pragma unroll
        for (int ks = 0; ks < 2; ks++) {
            const int c0 = ks * 16 + csel;
            unsigned AH_[4][4], AL_[4][4];
#pragma unroll
            for (int mt = 0; mt < 4; mt++) {
                const unsigned ad = sb + ((wm * 64 + mt * 16 + arow) * 40 + c0) * 2;
                ldsm4(AH_[mt][0], AH_[mt][1], AH_[mt][2], AH_[mt][3], ad);
            }
#pragma unroll
            for (int mt = 0; mt < 4; mt++) {
                const unsigned ad = sb + 10240 + ((wm * 64 + mt * 16 + arow) * 40 + c0) * 2;
                ldsm4(AL_[mt][0], AL_[mt][1], AL_[mt][2], AL_[mt][3], ad);
            }
#pragma unroll
            for (int nh = 0; nh < 2; nh++) {
                unsigned BH_[4][2], BL_[4][2];
#pragma unroll
                for (int p = 0; p < 2; p++) {
                    unsigned q0, q1, q2, q3;
                    const unsigned bd = sb + 20480 +
                        ((wn * 64 + nh * 32 + p * 16 + arow) * 40 + c0) * 2;
                    ldsm4(q0, q1, q2, q3, bd);
                    BH_[2 * p][0] = q0; BH_[2 * p][1] = q2;
                    BH_[2 * p + 1][0] = q1; BH_[2 * p + 1][1] = q3;
                    ldsm4(q0, q1, q2, q3, bd + 20480);
                    BL_[2 * p][0] = q0; BL_[2 * p][1] = q2;
                    BL_[2 * p + 1][0] = q1; BL_[2 * p + 1][1] = q3;
                }
#pragma unroll
                for (int mt = 0; mt < 4; mt++)
#pragma unroll
                    for (int nt = 0; nt < 4; nt++) {
                        float* a = acc[mt][nh * 4 + nt];
                        mma16816(a, AH_[mt], BH_[nt]);
                        mma16816(a, AH_[mt], BL_[nt]);
                        mma16816(a, AL_[mt], BH_[nt]);
                    }
            }
        }
        __syncthreads();
    }

#pragma unroll
    for (int mt = 0; mt < 4; mt++) {
        const int rr = wm * 64 + mt * 16 + g;
#pragma unroll
        for (int nt = 0; nt < 8; nt++) {
            const int cl = wn * 64 + nt * 8 + 2 * t4;
            float b0 = 0.f, b1 = 0.f;
            if (bias) {
                const int gcol = bx * 256 + cl;
                b0 = bias[gcol]; b1 = bias[gcol + 1];
            }
            float2 v0 = make_float2(acc[mt][nt][0] + b0, acc[mt][nt][1] + b1);
            float2 v1 = make_float2(acc[mt][nt][2] + b0, acc[mt][nt][3] + b1);
            *(float2*)(Cb + (size_t)rr * ldc + cl) = v0;
            *(float2*)(Cb + (size_t)(rr + 8) * ldc + cl) = v1;
        }
    }
}

// ---------------------------------------------------------------------------
// Fused flash attention (split-precision bf16 mma, causal) — as in R6 (passing).
// ---------------------------------------------------------------------------
#define OFF_QL   34816
#define OFF_KV   69632
#define STAGE_B  71680
#define OFF_KL   17408
#define OFF_VH   34816
#define OFF_VL   53248
#define SMEM_FLASH (OFF_KV + 2 * STAGE_B)   // 212992

__global__ __launch_bounds__(256) void flash_attn(float kl2)
{
    const int h  = blockIdx.y;
    const int by = 15 - blockIdx.x;        // heavy tiles first
    const int rowbase = by * 128;
    const int jmax = 2 * by + 1;
    const int hk = h >> 2;

    extern __shared__ bf16 smem[];
    const unsigned SB = (unsigned)__cvta_generic_to_shared(smem);

    const bf16* Qh = g_qkv_hi;
    const bf16* Ql = g_qkv_lo;
    const bf16* Kh = g_qkv_hi + HID;
    const bf16* Kl = g_qkv_lo + HID;
    const bf16* Vh = g_vt_hi + (size_t)hk * HD * SEQ;
    const bf16* Vl = g_vt_lo + (size_t)hk * HD * SEQ;

    const int tid  = threadIdx.x;
    const int w    = tid >> 5, lane = tid & 31;
    const int g    = lane >> 2, t4 = lane & 3;
    const int arow = lane & 15, csel = (lane >> 4) << 3;

    for (int c = tid; c < 2048; c += 256) {
        const int row = c >> 4, cc = c & 15;
        const unsigned dq = SB + row * 272 + cc * 16;
        const size_t go = (size_t)(rowbase + row) * QKVN + h * HD + cc * 8;
        CP16(dq,          Qh + go);
        CP16(dq + OFF_QL, Ql + go);
    }

    auto loadKV = [&](int st, int j) {
        const unsigned sb = SB + OFF_KV + st * STAGE_B;
        for (int c = tid; c < 1024; c += 256) {
            const int row = c >> 4, cc = c & 15;
            const unsigned d = sb + row * 272 + cc * 16;
            const size_t go = (size_t)(j * 64 + row) * QKVN + hk * HD + cc * 8;
            CP16(d,          Kh + go);
            CP16(d + OFF_KL, Kl + go);
        }
        for (int c = tid; c < 1024; c += 256) {
            const int row = c >> 3, cc = c & 7;
            const unsigned d = sb + OFF_VH + row * 144 + cc * 16;
            const size_t go = (size_t)row * SEQ + j * 64 + cc * 8;
            CP16(d,                     Vh + go);
            CP16(d + (OFF_VL - OFF_VH), Vl + go);
        }
    };

    loadKV(0, 0);
    CP_COMMIT();

    float O[16][4];
#pragma unroll
    for (int i = 0; i < 16; i++)
#pragma unroll
        for (int q = 0; q < 4; q++) O[i][q] = 0.f;
    float m0 = -1e30f, m1 = -1e30f, l0 = 0.f, l1 = 0.f;

    const int r0g = rowbase + w * 16 + g;

    for (int j = 0; j <= jmax; j++) {
        const int cur = j & 1;
        if (j < jmax) { loadKV(cur ^ 1, j + 1); CP_COMMIT(); CP_WAIT1(); }
        else          { CP_WAIT0(); }
        __syncthreads();

        const unsigned kb = SB + OFF_KV + cur * STAGE_B;

        float S[8][4];
#pragma unroll
        for (int i = 0; i < 8; i++)
#pragma unroll
            for (int q = 0; q < 4; q++) S[i][q] = 0.f;

#pragma unroll
        for (int ks = 0; ks < 8; ks++) {
            const int c0 = ks * 16 + csel;
            unsigned ah[4], al[4], BH_[8][2], BL_[8][2];
            const unsigned qa = SB + (w * 16 + arow) * 272 + c0 * 2;
            ldsm4(ah[0], ah[1], ah[2], ah[3], qa);
            ldsm4(al[0], al[1], al[2], al[3], qa + OFF_QL);
#pragma unroll
            for (int p = 0; p < 4; p++) {
                unsigned q0, q1, q2, q3;
                const unsigned ka = kb + (p * 16 + arow) * 272 + c0 * 2;
                ldsm4(q0, q1, q2, q3, ka);
                BH_[2 * p][0] = q0; BH_[2 * p][1] = q2;
                BH_[2 * p + 1][0] = q1; BH_[2 * p + 1][1] = q3;
                ldsm4(q0, q1, q2, q3, ka + OFF_KL);
                BL_[2 * p][0] = q0; BL_[2 * p][1] = q2;
                BL_[2 * p + 1][0] = q1; BL_[2 * p + 1][1] = q3;
            }
#pragma unroll
            for (int nt = 0; nt < 8; nt++) {
                mma16816(S[nt], ah, BH_[nt]);
                mma16816(S[nt], ah, BL_[nt]);
                mma16816(S[nt], al, BH_[nt]);
            }
        }

        if (j >= 2 * by) {
#pragma unroll
            for (int nt = 0; nt < 8; nt++) {
                const int colb = j * 64 + nt * 8 + 2 * t4;
                if (colb     > r0g)     S[nt][0] = -1e30f;
                if (colb + 1 > r0g)     S[nt][1] = -1e30f;
                if (colb     > r0g + 8) S[nt][2] = -1e30f;
                if (colb + 1 > r0g + 8) S[nt][3] = -1e30f;
            }
        }

        float mx0 = -1e30f, mx1 = -1e30f;
#pragma unroll
        for (int nt = 0; nt < 8; nt++) {
            mx0 = fmaxf(mx0, fmaxf(S[nt][0], S[nt][1]));
            mx1 = fmaxf(mx1, fmaxf(S[nt][2], S[nt][3]));
        }
        mx0 = fmaxf(mx0, __shfl_xor_sync(0xffffffffu, mx0, 1));
        mx0 = fmaxf(mx0, __shfl_xor_sync(0xffffffffu, mx0, 2));
        mx1 = fmaxf(mx1, __shfl_xor_sync(0xffffffffu, mx1, 1));
        mx1 = fmaxf(mx1, __shfl_xor_sync(0xffffffffu, mx1, 2));
        const float mn0 = fmaxf(m0, mx0), mn1 = fmaxf(m1, mx1);
        const float f0 = exp2f((m0 - mn0) * kl2);
        const float f1 = exp2f((m1 - mn1) * kl2);
        m0 = mn0; m1 = mn1;

        float s0 = 0.f, s1 = 0.f;
#pragma unroll
        for (int nt = 0; nt < 8; nt++) {
            S[nt][0] = exp2f((S[nt][0] - m0) * kl2);
            S[nt][1] = exp2f((S[nt][1] - m0) * kl2);
            S[nt][2] = exp2f((S[nt][2] - m1) * kl2);
            S[nt][3] = exp2f((S[nt][3] - m1) * kl2);
            s0 += S[nt][0] + S[nt][1];
            s1 += S[nt][2] + S[nt][3];
        }
        s0 += __shfl_xor_sync(0xffffffffu, s0, 1);
        s0 += __shfl_xor_sync(0xffffffffu, s0, 2);
        s1 += __shfl_xor_sync(0xffffffffu, s1, 1);
        s1 += __shfl_xor_sync(0xffffffffu, s1, 2);
        l0 = l0 * f0 + s0;
        l1 = l1 * f1 + s1;
#pragma unroll
        for (int i = 0; i < 16; i++) {
            O[i][0] *= f0; O[i][1] *= f0;
            O[i][2] *= f1; O[i][3] *= f1;
        }

        unsigned Ph[4][4], Pl[4][4];
#pragma unroll
        for (int kt = 0; kt < 4; kt++) {
            pack_hl(S[2 * kt][0],     S[2 * kt][1],     Ph[kt][0], Pl[kt][0]);
            pack_hl(S[2 * kt][2],     S[2 * kt][3],     Ph[kt][1], Pl[kt][1]);
            pack_hl(S[2 * kt + 1][0], S[2 * kt + 1][1], Ph[kt][2], Pl[kt][2]);
            pack_hl(S[2 * kt + 1][2], S[2 * kt + 1][3], Ph[kt][3], Pl[kt][3]);
        }

#pragma unroll
        for (int p = 0; p < 8; p++) {
#pragma unroll
            for (int ks = 0; ks < 4; ks++) {
                unsigned v0, v1, v2, v3, u0, u1, u2, u3;
                const unsigned va = kb + OFF_VH + (p * 16 + arow) * 144 + (ks * 16 + csel) * 2;
                ldsm4(v0, v1, v2, v3, va);
                ldsm4(u0, u1, u2, u3, va + (OFF_VL - OFF_VH));
                unsigned bh0[2] = {v0, v2}, bh1[2] = {v1, v3};
                unsigned bl0[2] = {u0, u2}, bl1[2] = {u1, u3};
                mma16816(O[2 * p],     Ph[ks], bh0);
                mma16816(O[2 * p],     Ph[ks], bl0);
                mma16816(O[2 * p],     Pl[ks], bh0);
                mma16816(O[2 * p + 1], Ph[ks], bh1);
                mma16816(O[2 * p + 1], Ph[ks], bl1);
                mma16816(O[2 * p + 1], Pl[ks], bh1);
            }
        }
        __syncthreads();
    }

    const float i0 = 1.f / l0, i1 = 1.f / l1;
#pragma unroll
    for (int nt = 0; nt < 16; nt++) {
        const int d = nt * 8 + 2 * t4;
        unsigned uh, ul;
        pack_hl(O[nt][0] * i0, O[nt][1] * i0, uh, ul);
        const size_t o0 = (size_t)r0g * HID + h * HD + d;
        *(unsigned*)&g_attn_hi[o0] = uh;
        *(unsigned*)&g_attn_lo[o0] = ul;
        pack_hl(O[nt][2] * i1, O[nt][3] * i1, uh, ul);
        const size_t o1 = (size_t)(r0g + 8) * HID + h * HD + d;
        *(unsigned*)&g_attn_hi[o1] = uh;
        *(unsigned*)&g_attn_lo[o1] = ul;
    }
}

// ------------------------- RoPE (in-place, fp32 qkv) ------------------------
__global__ void rope_kernel(const int* __restrict__ positions)
{
    const int total = SEQ * 40 * 64;
    int idx = blockIdx.x * blockDim.x + threadIdx.x;
    if (idx >= total) return;
    const int i    = idx & 63;
    const int head = (idx >> 6) % 40;   // 0..31 Q, 32..39 K
    const int s    = idx / (40 * 64);

    float* base = g_qkv + (size_t)s * QKVN +
                  (head < 32 ? head * HD : HID + (head - 32) * HD);

    const double pos = (double)positions[s];
    const double inv_freq = exp(-(double)i * (9.210340371976184 / 64.0));
    const double a = pos * inv_freq;
    const float c  = (float)cos(a);
    const float sn = (float)sin(a);

    const float x1 = base[i];
    const float x2 = base[i + 64];
    base[i]      = x1 * c - x2 * sn;
    base[i + 64] = x2 * c + x1 * sn;
}

// ---------------------------------------------------------------------------
extern "C" void kernel_launch(void* const* d_in, const int* in_sizes, int n_in,
                              void* d_out, int out_size)
{
    const int*   positions = (const int*)d_in[0];
    const float* hidden    = (const float*)d_in[1];
    const float* Wqkv      = (const float*)d_in[2];
    const float* bqkv      = (const float*)d_in[3];
    const float* Wproj     = (const float*)d_in[4];
    const float* bproj     = (const float*)d_in[5];
    float* out = (float*)d_out;

    bf16 *hid_hi, *hid_lo, *wqkvT_hi, *wqkvT_lo, *wprojT_hi, *wprojT_lo;
    bf16 *qkv_hi, *qkv_lo, *vt_hi, *vt_lo, *attn_hi, *attn_lo;
    float *qkv_p;
    cudaGetSymbolAddress((void**)&hid_hi,    g_hid_hi);
    cudaGetSymbolAddress((void**)&hid_lo,    g_hid_lo);
    cudaGetSymbolAddress((void**)&wqkvT_hi,  g_wqkvT_hi);
    cudaGetSymbolAddress((void**)&wqkvT_lo,  g_wqkvT_lo);
    cudaGetSymbolAddress((void**)&wprojT_hi, g_wprojT_hi);
    cudaGetSymbolAddress((void**)&wprojT_lo, g_wprojT_lo);
    cudaGetSymbolAddress((void**)&qkv_p,     g_qkv);
    cudaGetSymbolAddress((void**)&qkv_hi,    g_qkv_hi);
    cudaGetSymbolAddress((void**)&qkv_lo,    g_qkv_lo);
    cudaGetSymbolAddress((void**)&vt_hi,     g_vt_hi);
    cudaGetSymbolAddress((void**)&vt_lo,     g_vt_lo);
    cudaGetSymbolAddress((void**)&attn_hi,   g_attn_hi);
    cudaGetSymbolAddress((void**)&attn_lo,   g_attn_lo);

    cudaFuncSetAttribute(gemm3p, cudaFuncAttributeMaxDynamicSharedMemorySize, GP_SMEM);
    cudaFuncSetAttribute(flash_attn, cudaFuncAttributeMaxDynamicSharedMemorySize, SMEM_FLASH);

    const float scale = 1.0f / sqrtf((float)HD);
    const float kl2   = scale * 1.4426950408889634f;

    // 0) splits: hidden (plain), Wqkv/Wproj (transposed)
    {
        size_t n1 = (size_t)SEQ * HID;
        split_f32<<<(unsigned)((n1/4 + 255)/256), 256>>>(hidden, hid_hi, hid_lo, n1);
        dim3 tb(32, 8);
        tsplit_f32<<<dim3(QKVN/32, HID/32, 1), tb>>>(Wqkv, QKVN, 0, wqkvT_hi, wqkvT_lo, HID, 0);
        tsplit_f32<<<dim3(HID/32, HID/32, 1),  tb>>>(Wproj, HID, 0, wprojT_hi, wprojT_lo, HID, 0);
    }

    // 1) QKV projection: [2048,4096] @ [4096,6144] + bias
    gemm3p<<<dim3(QKVN/256, SEQ/128), 256, GP_SMEM>>>(
        HID, hid_hi, hid_lo, HID, wqkvT_hi, wqkvT_lo, HID,
        bqkv, qkv_p, QKVN);

    // 2) RoPE on Q and K
    rope_kernel<<<(SEQ * 40 * 64 + 255) / 256, 256>>>(positions);

    // 3) split qkv; transpose-split V per KV head
    {
        size_t n = (size_t)SEQ * QKVN;
        split_f32<<<(unsigned)((n/4 + 255)/256), 256>>>(qkv_p, qkv_hi, qkv_lo, n);
        dim3 tb(32, 8);
        tsplit_f32<<<dim3(HD/32, SEQ/32, NKVH), tb>>>(
            qkv_p + HID + KVD, QKVN, HD, vt_hi, vt_lo, SEQ, (long long)HD * SEQ);
    }

    // 4) fused flash attention -> attn hi/lo
    flash_attn<<<dim3(16, NQH), 256, SMEM_FLASH>>>(kl2);

    // 5) output projection: [2048,4096] @ [4096,4096] + bias
    gemm3p<<<dim3(HID/256, SEQ/128), 256, GP_SMEM>>>(
        HID, attn_hi, attn_lo, HID, wprojT_hi, wprojT_lo, HID,
        bproj, out, HID);
}

// round 9
// speedup vs baseline: 1.3563x; 1.3563x over previous
#include <cuda_runtime.h>
#include <cuda_fp16.h>
#include <math.h>

#define SEQ   2048
#define HID   4096
#define NQH   32
#define NKVH  8
#define HD    128
#define KVD   1024
#define QKVN  6144   // 4096 + 2*1024

// ------------------------- device scratch (no allocation allowed) ----------
__device__ __align__(16) __half g_hid_hi[(size_t)SEQ * HID];
__device__ __align__(16) __half g_hid_lo[(size_t)SEQ * HID];
__device__ __align__(16) __half g_wqkvT[(size_t)QKVN * HID];    // [N][K] single fp16
__device__ __align__(16) __half g_wprojT[(size_t)HID * HID];    // [N][K] single fp16
__device__ __align__(16) float  g_qkv[(size_t)SEQ * QKVN];
__device__ __align__(16) __half g_qkv_hi[(size_t)SEQ * QKVN];
__device__ __align__(16) __half g_qkv_lo[(size_t)SEQ * QKVN];
__device__ __align__(16) __half g_vt[(size_t)NKVH * HD * SEQ];  // [h][d][t] single fp16
__device__ __align__(16) __half g_attn_hi[(size_t)SEQ * HID];
__device__ __align__(16) __half g_attn_lo[(size_t)SEQ * HID];

// ------------------------- PTX helpers --------------------------------------
__device__ __forceinline__ void mma16816h(float* c, const unsigned* a, const unsigned* b)
{
    asm volatile(
        "mma.sync.aligned.m16n8k16.row.col.f32.f16.f16.f32 "
        "{%0,%1,%2,%3}, {%4,%5,%6,%7}, {%8,%9}, {%0,%1,%2,%3};\n"
        : "+f"(c[0]), "+f"(c[1]), "+f"(c[2]), "+f"(c[3])
        : "r"(a[0]), "r"(a[1]), "r"(a[2]), "r"(a[3]), "r"(b[0]), "r"(b[1]));
}
__device__ __forceinline__ void ldsm4(unsigned& r0, unsigned& r1, unsigned& r2, unsigned& r3,
                                      unsigned addr)
{
    asm volatile("ldmatrix.sync.aligned.m8n8.x4.shared.b16 {%0,%1,%2,%3}, [%4];\n"
                 : "=r"(r0), "=r"(r1), "=r"(r2), "=r"(r3) : "r"(addr));
}
#define CP16(dst, src) \
    asm volatile("cp.async.cg.shared.global [%0], [%1], 16;\n" :: "r"(dst), "l"(src))
#define CP_COMMIT() asm volatile("cp.async.commit_group;\n")
#define CP_WAIT1()  asm volatile("cp.async.wait_group 1;\n")
#define CP_WAIT0()  asm volatile("cp.async.wait_group 0;\n")

__device__ __forceinline__ void pack_hl16(float a, float b, unsigned& h, unsigned& l)
{
    __half ha = __float2half_rn(a), hb = __float2half_rn(b);
    __half2 hh = __halves2half2(ha, hb);
    h = *(unsigned*)&hh;
    __half la = __float2half_rn(a - __half2float(ha));
    __half lb = __float2half_rn(b - __half2float(hb));
    __half2 ll = __halves2half2(la, lb);
    l = *(unsigned*)&ll;
}

// ------------------------- split fp32 -> (hi, lo) fp16 ----------------------
__global__ void split_f16(const float* __restrict__ in,
                          __half* __restrict__ hi, __half* __restrict__ lo, size_t n)
{
    size_t i = ((size_t)blockIdx.x * blockDim.x + threadIdx.x) * 4;
    if (i >= n) return;
    float4 v = *(const float4*)(in + i);
    __half h0 = __float2half_rn(v.x), h1 = __float2half_rn(v.y);
    __half h2 = __float2half_rn(v.z), h3 = __float2half_rn(v.w);
    hi[i] = h0; hi[i+1] = h1; hi[i+2] = h2; hi[i+3] = h3;
    lo[i]   = __float2half_rn(v.x - __half2float(h0));
    lo[i+1] = __float2half_rn(v.y - __half2float(h1));
    lo[i+2] = __float2half_rn(v.z - __half2float(h2));
    lo[i+3] = __float2half_rn(v.w - __half2float(h3));
}

// -------- transposed convert: in[k][n] fp32 -> out[n][k] single fp16 --------
__global__ void ttofp16(const float* __restrict__ in, int ldin, long long inZ,
                        __half* __restrict__ out, int ldout, long long outZ)
{
    __shared__ float t[32][33];
    const float* I = in + (size_t)blockIdx.z * inZ;
    __half* O = out + (size_t)blockIdx.z * outZ;
    const int k0 = blockIdx.y * 32, n0 = blockIdx.x * 32;
    const int tx = threadIdx.x, ty = threadIdx.y;   // 32 x 8
#pragma unroll
    for (int i = 0; i < 32; i += 8)
        t[ty + i][tx] = I[(size_t)(k0 + ty + i) * ldin + n0 + tx];
    __syncthreads();
#pragma unroll
    for (int i = 0; i < 32; i += 8)
        O[(size_t)(n0 + ty + i) * ldout + k0 + tx] = __float2half_rn(t[tx][ty + i]);
}

// ---------------------------------------------------------------------------
// 2-product fp16 GEMM (dense projections): C = Ah*B + Al*B + bias
// A: [M,K] row-major split hi/lo. B: [N,K] row-major single fp16.
// Tile 128(M) x 256(N), BK=32, 256 threads, 8 warps (2x4), warp 64x64.
// stage: Ah@0 (10240) Al@10240 B@20480 (20480) -> 40960 B
// ---------------------------------------------------------------------------
#define GP_STAGE 40960
#define GP_SMEM  (2 * GP_STAGE)   // 81920

__global__ __launch_bounds__(256, 1) void gemm2p(
    int K,
    const __half* __restrict__ Ahi, const __half* __restrict__ Alo, int lda,
    const __half* __restrict__ B, int ldb,
    const float* __restrict__ bias,
    float* __restrict__ C, int ldc)
{
    const int bx = blockIdx.x, by = blockIdx.y;

    extern __shared__ __half smem[];
    const unsigned SB = (unsigned)__cvta_generic_to_shared(smem);

    float* Cb = C + (size_t)by * 128 * ldc + (size_t)bx * 256;

    const int tid  = threadIdx.x;
    const int warp = tid >> 5, lane = tid & 31;
    const int wm = warp >> 2, wn = warp & 3;        // 2 x 4 warps
    const int g = lane >> 2, t4 = lane & 3;
    const int arow = lane & 15, csel = (lane >> 4) << 3;

    const int r = tid >> 2;                         // 0..63
    const int ch = tid & 3;                         // 16B chunk

    const int nk = K >> 5;

    auto loadStage = [&](int s, int kt) {
        const int k0 = kt * 32 + ch * 8;
        const unsigned sb = SB + s * GP_STAGE;
        const unsigned dof = r * 80 + ch * 16;
#pragma unroll
        for (int i = 0; i < 2; i++) {               // A hi/lo: 128 rows
            const int row = r + i * 64;
            const unsigned d = sb + dof + i * 64 * 80;
            CP16(d,         Ahi + (size_t)(by * 128 + row) * lda + k0);
            CP16(d + 10240, Alo + (size_t)(by * 128 + row) * lda + k0);
        }
#pragma unroll
        for (int i = 0; i < 4; i++) {               // B: 256 rows
            const int row = r + i * 64;
            CP16(sb + 20480 + dof + i * 64 * 80,
                 B + (size_t)(bx * 256 + row) * ldb + k0);
        }
    };

    float acc[4][8][4];
#pragma unroll
    for (int i = 0; i < 4; i++)
#pragma unroll
        for (int j = 0; j < 8; j++)
#pragma unroll
            for (int q = 0; q < 4; q++) acc[i][j][q] = 0.f;

    loadStage(0, 0);
    CP_COMMIT();

    for (int kt = 0; kt < nk; kt++) {
        const int cur = kt & 1;
        if (kt + 1 < nk) { loadStage(cur ^ 1, kt + 1); CP_COMMIT(); CP_WAIT1(); }
        else            { CP_WAIT0(); }
        __syncthreads();

        const unsigned sb = SB + cur * GP_STAGE;
#pragma unroll
        for (int ks = 0; ks < 2; ks++) {
            const int c0 = ks * 16 + csel;
            unsigned AH_[4][4], AL_[4][4];
#pragma unroll
            for (int mt = 0; mt < 4; mt++) {
                const unsigned ad = sb + ((wm * 64 + mt * 16 + arow) * 40 + c0) * 2;
                ldsm4(AH_[mt][0], AH_[mt][1], AH_[mt][2], AH_[mt][3], ad);
            }
#pragma unroll
            for (int mt = 0; mt < 4; mt++) {
                const unsigned ad = sb + 10240 + ((wm * 64 + mt * 16 + arow) * 40 + c0) * 2;
                ldsm4(AL_[mt][0], AL_[mt][1], AL_[mt][2], AL_[mt][3], ad);
            }
#pragma unroll
            for (int nh = 0; nh < 2; nh++) {
                unsigned B_[4][2];
#pragma unroll
                for (int p = 0; p < 2; p++) {
                    unsigned q0, q1, q2, q3;
                    const unsigned bd = sb + 20480 +
                        ((wn * 64 + nh * 32 + p * 16 + arow) * 40 + c0) * 2;
                    ldsm4(q0, q1, q2, q3, bd);
                    B_[2 * p][0] = q0; B_[2 * p][1] = q2;
                    B_[2 * p + 1][0] = q1; B_[2 * p + 1][1] = q3;
                }
#pragma unroll
                for (int mt = 0; mt < 4; mt++)
#pragma unroll
                    for (int nt = 0; nt < 4; nt++) {
                        float* a = acc[mt][nh * 4 + nt];
                        mma16816h(a, AH_[mt], B_[nt]);
                        mma16816h(a, AL_[mt], B_[nt]);
                    }
            }
        }
        __syncthreads();
    }

#pragma unroll
    for (int mt = 0; mt < 4; mt++) {
        const int rr = wm * 64 + mt * 16 + g;
#pragma unroll
        for (int nt = 0; nt < 8; nt++) {
            const int cl = wn * 64 + nt * 8 + 2 * t4;
            float b0 = 0.f, b1 = 0.f;
            if (bias) {
                const int gcol = bx * 256 + cl;
                b0 = bias[gcol]; b1 = bias[gcol + 1];
            }
            float2 v0 = make_float2(acc[mt][nt][0] + b0, acc[mt][nt][1] + b1);
            float2 v1 = make_float2(acc[mt][nt][2] + b0, acc[mt][nt][3] + b1);
            *(float2*)(Cb + (size_t)rr * ldc + cl) = v0;
            *(float2*)(Cb + (size_t)(rr + 8) * ldc + cl) = v1;
        }
    }
}

// ---------------------------------------------------------------------------
// Fused flash attention (fp16 2-product, causal).
// CTA: 128 Q rows x 1 head. 8 warps. KV blocks of 64.
// smem: Q hi/lo resident (2 x 34816); per stage: K single 17408 + V single 18432.
// ---------------------------------------------------------------------------
#define OFF_QL   34816
#define OFF_KV   69632
#define STAGE_B  35840
#define OFF_V    17408
#define SMEM_FLASH (OFF_KV + 2 * STAGE_B)   // 141312

__global__ __launch_bounds__(256) void flash_attn(float kl2)
{
    const int h  = blockIdx.y;
    const int by = 15 - blockIdx.x;        // heavy tiles first
    const int rowbase = by * 128;
    const int jmax = 2 * by + 1;
    const int hk = h >> 2;

    extern __shared__ __half smem[];
    const unsigned SB = (unsigned)__cvta_generic_to_shared(smem);

    const __half* Qh = g_qkv_hi;
    const __half* Ql = g_qkv_lo;
    const __half* Kf = g_qkv_hi + HID;                       // K single (hi of split)
    const __half* Vf = g_vt + (size_t)hk * HD * SEQ;

    const int tid  = threadIdx.x;
    const int w    = tid >> 5, lane = tid & 31;
    const int g    = lane >> 2, t4 = lane & 3;
    const int arow = lane & 15, csel = (lane >> 4) << 3;

    // Q tile hi+lo -> smem
    for (int c = tid; c < 2048; c += 256) {
        const int row = c >> 4, cc = c & 15;
        const unsigned dq = SB + row * 272 + cc * 16;
        const size_t go = (size_t)(rowbase + row) * QKVN + h * HD + cc * 8;
        CP16(dq,          Qh + go);
        CP16(dq + OFF_QL, Ql + go);
    }

    auto loadKV = [&](int st, int j) {
        const unsigned sb = SB + OFF_KV + st * STAGE_B;
        for (int c = tid; c < 1024; c += 256) {
            const int row = c >> 4, cc = c & 15;
            CP16(sb + row * 272 + cc * 16,
                 Kf + (size_t)(j * 64 + row) * QKVN + hk * HD + cc * 8);
        }
        for (int c = tid; c < 1024; c += 256) {
            const int row = c >> 3, cc = c & 7;
            CP16(sb + OFF_V + row * 144 + cc * 16,
                 Vf + (size_t)row * SEQ + j * 64 + cc * 8);
        }
    };

    loadKV(0, 0);
    CP_COMMIT();

    float O[16][4];
#pragma unroll
    for (int i = 0; i < 16; i++)
#pragma unroll
        for (int q = 0; q < 4; q++) O[i][q] = 0.f;
    float m0 = -1e30f, m1 = -1e30f, l0 = 0.f, l1 = 0.f;

    const int r0g = rowbase + w * 16 + g;

    for (int j = 0; j <= jmax; j++) {
        const int cur = j & 1;
        if (j < jmax) { loadKV(cur ^ 1, j + 1); CP_COMMIT(); CP_WAIT1(); }
        else          { CP_WAIT0(); }
        __syncthreads();

        const unsigned kb = SB + OFF_KV + cur * STAGE_B;

        // S = (Qh + Ql) K^T, 2 products
        float S[8][4];
#pragma unroll
        for (int i = 0; i < 8; i++)
#pragma unroll
            for (int q = 0; q < 4; q++) S[i][q] = 0.f;

#pragma unroll
        for (int ks = 0; ks < 8; ks++) {
            const int c0 = ks * 16 + csel;
            unsigned ah[4], al[4], B_[8][2];
            const unsigned qa = SB + (w * 16 + arow) * 272 + c0 * 2;
            ldsm4(ah[0], ah[1], ah[2], ah[3], qa);
            ldsm4(al[0], al[1], al[2], al[3], qa + OFF_QL);
#pragma unroll
            for (int p = 0; p < 4; p++) {
                unsigned q0, q1, q2, q3;
                ldsm4(q0, q1, q2, q3, kb + (p * 16 + arow) * 272 + c0 * 2);
                B_[2 * p][0] = q0; B_[2 * p][1] = q2;
                B_[2 * p + 1][0] = q1; B_[2 * p + 1][1] = q3;
            }
#pragma unroll
            for (int nt = 0; nt < 8; nt++) {
                mma16816h(S[nt], ah, B_[nt]);
                mma16816h(S[nt], al, B_[nt]);
            }
        }

        // causal mask (diagonal blocks only)
        if (j >= 2 * by) {
#pragma unroll
            for (int nt = 0; nt < 8; nt++) {
                const int colb = j * 64 + nt * 8 + 2 * t4;
                if (colb     > r0g)     S[nt][0] = -1e30f;
                if (colb + 1 > r0g)     S[nt][1] = -1e30f;
                if (colb     > r0g + 8) S[nt][2] = -1e30f;
                if (colb + 1 > r0g + 8) S[nt][3] = -1e30f;
            }
        }

        // online softmax
        float mx0 = -1e30f, mx1 = -1e30f;
#pragma unroll
        for (int nt = 0; nt < 8; nt++) {
            mx0 = fmaxf(mx0, fmaxf(S[nt][0], S[nt][1]));
            mx1 = fmaxf(mx1, fmaxf(S[nt][2], S[nt][3]));
        }
        mx0 = fmaxf(mx0, __shfl_xor_sync(0xffffffffu, mx0, 1));
        mx0 = fmaxf(mx0, __shfl_xor_sync(0xffffffffu, mx0, 2));
        mx1 = fmaxf(mx1, __shfl_xor_sync(0xffffffffu, mx1, 1));
        mx1 = fmaxf(mx1, __shfl_xor_sync(0xffffffffu, mx1, 2));
        const float mn0 = fmaxf(m0, mx0), mn1 = fmaxf(m1, mx1);
        const float f0 = exp2f((m0 - mn0) * kl2);
        const float f1 = exp2f((m1 - mn1) * kl2);
        m0 = mn0; m1 = mn1;

        float s0 = 0.f, s1 = 0.f;
#pragma unroll
        for (int nt = 0; nt < 8; nt++) {
            S[nt][0] = exp2f((S[nt][0] - m0) * kl2);
            S[nt][1] = exp2f((S[nt][1] - m0) * kl2);
            S[nt][2] = exp2f((S[nt][2] - m1) * kl2);
            S[nt][3] = exp2f((S[nt][3] - m1) * kl2);
            s0 += S[nt][0] + S[nt][1];
            s1 += S[nt][2] + S[nt][3];
        }
        s0 += __shfl_xor_sync(0xffffffffu, s0, 1);
        s0 += __shfl_xor_sync(0xffffffffu, s0, 2);
        s1 += __shfl_xor_sync(0xffffffffu, s1, 1);
        s1 += __shfl_xor_sync(0xffffffffu, s1, 2);
        l0 = l0 * f0 + s0;
        l1 = l1 * f1 + s1;
#pragma unroll
        for (int i = 0; i < 16; i++) {
            O[i][0] *= f0; O[i][1] *= f0;
            O[i][2] *= f1; O[i][3] *= f1;
        }

        // pack P -> hi/lo fp16 A-fragments (registers)
        unsigned Ph[4][4], Pl[4][4];
#pragma unroll
        for (int kt = 0; kt < 4; kt++) {
            pack_hl16(S[2 * kt][0],     S[2 * kt][1],     Ph[kt][0], Pl[kt][0]);
            pack_hl16(S[2 * kt][2],     S[2 * kt][3],     Ph[kt][1], Pl[kt][1]);
            pack_hl16(S[2 * kt + 1][0], S[2 * kt + 1][1], Ph[kt][2], Pl[kt][2]);
            pack_hl16(S[2 * kt + 1][2], S[2 * kt + 1][3], Ph[kt][3], Pl[kt][3]);
        }

        // O += (Ph + Pl) V, 2 products. V^T rows = d (128), cols = t (64)
#pragma unroll
        for (int p = 0; p < 8; p++) {
#pragma unroll
            for (int ks = 0; ks < 4; ks++) {
                unsigned v0, v1, v2, v3;
                ldsm4(v0, v1, v2, v3,
                      kb + OFF_V + (p * 16 + arow) * 144 + (ks * 16 + csel) * 2);
                unsigned b0[2] = {v0, v2}, b1[2] = {v1, v3};
                mma16816h(O[2 * p],     Ph[ks], b0);
                mma16816h(O[2 * p],     Pl[ks], b0);
                mma16816h(O[2 * p + 1], Ph[ks], b1);
                mma16816h(O[2 * p + 1], Pl[ks], b1);
            }
        }
        __syncthreads();
    }

    // epilogue: normalize, split hi/lo fp16, store
    const float i0 = 1.f / l0, i1 = 1.f / l1;
#pragma unroll
    for (int nt = 0; nt < 16; nt++) {
        const int d = nt * 8 + 2 * t4;
        unsigned uh, ul;
        pack_hl16(O[nt][0] * i0, O[nt][1] * i0, uh, ul);
        const size_t o0 = (size_t)r0g * HID + h * HD + d;
        *(unsigned*)&g_attn_hi[o0] = uh;
        *(unsigned*)&g_attn_lo[o0] = ul;
        pack_hl16(O[nt][2] * i1, O[nt][3] * i1, uh, ul);
        const size_t o1 = (size_t)(r0g + 8) * HID + h * HD + d;
        *(unsigned*)&g_attn_hi[o1] = uh;
        *(unsigned*)&g_attn_lo[o1] = ul;
    }
}

// ------------------------- RoPE (in-place, fp32 qkv) ------------------------
__global__ void rope_kernel(const int* __restrict__ positions)
{
    const int total = SEQ * 40 * 64;
    int idx = blockIdx.x * blockDim.x + threadIdx.x;
    if (idx >= total) return;
    const int i    = idx & 63;
    const int head = (idx >> 6) % 40;   // 0..31 Q, 32..39 K
    const int s    = idx / (40 * 64);

    float* base = g_qkv + (size_t)s * QKVN +
                  (head < 32 ? head * HD : HID + (head - 32) * HD);

    const double pos = (double)positions[s];
    const double inv_freq = exp(-(double)i * (9.210340371976184 / 64.0));
    const double a = pos * inv_freq;
    const float c  = (float)cos(a);
    const float sn = (float)sin(a);

    const float x1 = base[i];
    const float x2 = base[i + 64];
    base[i]      = x1 * c - x2 * sn;
    base[i + 64] = x2 * c + x1 * sn;
}

// ---------------------------------------------------------------------------
extern "C" void kernel_launch(void* const* d_in, const int* in_sizes, int n_in,
                              void* d_out, int out_size)
{
    const int*   positions = (const int*)d_in[0];
    const float* hidden    = (const float*)d_in[1];
    const float* Wqkv      = (const float*)d_in[2];
    const float* bqkv      = (const float*)d_in[3];
    const float* Wproj     = (const float*)d_in[4];
    const float* bproj     = (const float*)d_in[5];
    float* out = (float*)d_out;

    __half *hid_hi, *hid_lo, *wqkvT, *wprojT;
    __half *qkv_hi, *qkv_lo, *vt, *attn_hi, *attn_lo;
    float *qkv_p;
    cudaGetSymbolAddress((void**)&hid_hi,  g_hid_hi);
    cudaGetSymbolAddress((void**)&hid_lo,  g_hid_lo);
    cudaGetSymbolAddress((void**)&wqkvT,   g_wqkvT);
    cudaGetSymbolAddress((void**)&wprojT,  g_wprojT);
    cudaGetSymbolAddress((void**)&qkv_p,   g_qkv);
    cudaGetSymbolAddress((void**)&qkv_hi,  g_qkv_hi);
    cudaGetSymbolAddress((void**)&qkv_lo,  g_qkv_lo);
    cudaGetSymbolAddress((void**)&vt,      g_vt);
    cudaGetSymbolAddress((void**)&attn_hi, g_attn_hi);
    cudaGetSymbolAddress((void**)&attn_lo, g_attn_lo);

    cudaFuncSetAttribute(gemm2p, cudaFuncAttributeMaxDynamicSharedMemorySize, GP_SMEM);
    cudaFuncSetAttribute(flash_attn, cudaFuncAttributeMaxDynamicSharedMemorySize, SMEM_FLASH);

    const float scale = 1.0f / sqrtf((float)HD);
    const float kl2   = scale * 1.4426950408889634f;

    // 0) prepare operands: hidden split fp16, weights transposed single fp16
    {
        size_t n1 = (size_t)SEQ * HID;
        split_f16<<<(unsigned)((n1/4 + 255)/256), 256>>>(hidden, hid_hi, hid_lo, n1);
        dim3 tb(32, 8);
        ttofp16<<<dim3(QKVN/32, HID/32, 1), tb>>>(Wqkv, QKVN, 0, wqkvT, HID, 0);
        ttofp16<<<dim3(HID/32, HID/32, 1),  tb>>>(Wproj, HID, 0, wprojT, HID, 0);
    }

    // 1) QKV projection: [2048,4096] @ [4096,6144] + bias
    gemm2p<<<dim3(QKVN/256, SEQ/128), 256, GP_SMEM>>>(
        HID, hid_hi, hid_lo, HID, wqkvT, HID, bqkv, qkv_p, QKVN);

    // 2) RoPE on Q and K
    rope_kernel<<<(SEQ * 40 * 64 + 255) / 256, 256>>>(positions);

    // 3) split qkv (hi/lo fp16 for Q,K); V^T single fp16 per KV head
    {
        size_t n = (size_t)SEQ * QKVN;
        split_f16<<<(unsigned)((n/4 + 255)/256), 256>>>(qkv_p, qkv_hi, qkv_lo, n);
        dim3 tb(32, 8);
        ttofp16<<<dim3(HD/32, SEQ/32, NKVH), tb>>>(
            qkv_p + HID + KVD, QKVN, HD, vt, SEQ, (long long)HD * SEQ);
    }

    // 4) fused flash attention -> attn hi/lo fp16
    flash_attn<<<dim3(16, NQH), 256, SMEM_FLASH>>>(kl2);

    // 5) output projection: [2048,4096] @ [4096,4096] + bias
    gemm2p<<<dim3(HID/256, SEQ/128), 256, GP_SMEM>>>(
        HID, attn_hi, attn_lo, HID, wprojT, HID, bproj, out, HID);
}